// round 16
// baseline (speedup 1.0000x reference)
#include <cuda_runtime.h>
#include <cuda_fp16.h>
#include <cstdint>

#define B_    8
#define N_    8192
#define M_    2048
#define C1_   128
#define C2_   256
#define H1_   256
#define H2_   128
#define CIN_  (C2_ + C1_)   // 384
#define BNPTS (B_ * N_)     // 65536
#define NC1   12            // K chunks layer 1 (384/32)
#define NC2   8             // K chunks layer 2 (256/32)

// strides in HALVES, conflict-free for ldmatrix
#define SA_H   40    // A / B1 / W2 chunk row stride
#define HSTR_H 264   // h row stride

#define A_BUFH  (128 * SA_H)     // 5120 halves
#define B1_BUFH (256 * SA_H)     // 10240
#define W2_BUFH (128 * SA_H)     // 5120
#define OFF_A0  0
#define OFF_A1  A_BUFH
#define OFF_B1  (2 * A_BUFH)               // 10240, 3 bufs -> ends 40960
#define OFF_H   0                          // overlays A + B1 region
#define OFF_W2  (OFF_B1 + 3 * B1_BUFH)     // 40960, 3 bufs (non-overlapping)
#define U_HALVES (OFF_W2 + 3 * W2_BUFH)    // 56320 halves = 112640 B
#define META_FLOATS 1152
#define SMEM_BYTES (META_FLOATS * 4 + U_HALVES * 2)   // 117248

// ---------------- scratch ----------------------------------------------------
__device__ int    g_idx[BNPTS * 3];
__device__ float  g_w[BNPTS * 3];
__device__ __half g_W1t[H1_ * CIN_];          // W1^T [n][k]
__device__ __half g_W2t[H2_ * H1_];           // W2^T [n][k]
__device__ __half g_p2h[B_ * M_ * C2_];       // points2 as half
__device__ __half g_p1h[(size_t)BNPTS * C1_]; // points1 as half

__device__ __forceinline__ void cp_async16(uint32_t dst, const void* src) {
    asm volatile("cp.async.ca.shared.global [%0], [%1], 16;"
                 :: "r"(dst), "l"(src) : "memory");
}
__device__ __forceinline__ void cp_commit() {
    asm volatile("cp.async.commit_group;" ::: "memory");
}
template<int NWAIT>
__device__ __forceinline__ void cp_wait() {
    asm volatile("cp.async.wait_group %0;" :: "n"(NWAIT) : "memory");
}
__device__ __forceinline__ uint32_t smem_u32(const void* p) {
    uint32_t a;
    asm("{ .reg .u64 t; cvta.to.shared.u64 t, %1; cvt.u32.u64 %0, t; }" : "=r"(a) : "l"(p));
    return a;
}
__device__ __forceinline__ void mma_f16(float* c, const uint32_t* a,
                                        const uint32_t* b) {
    asm volatile(
        "mma.sync.aligned.m16n8k16.row.col.f32.f16.f16.f32 "
        "{%0,%1,%2,%3}, {%4,%5,%6,%7}, {%8,%9}, {%0,%1,%2,%3};"
        : "+f"(c[0]), "+f"(c[1]), "+f"(c[2]), "+f"(c[3])
        : "r"(a[0]), "r"(a[1]), "r"(a[2]), "r"(a[3]), "r"(b[0]), "r"(b[1]));
}
__device__ __forceinline__ void ldsm_x4(uint32_t& r0, uint32_t& r1,
                                        uint32_t& r2, uint32_t& r3, uint32_t a) {
    asm volatile("ldmatrix.sync.aligned.m8n8.x4.shared.b16 {%0,%1,%2,%3}, [%4];"
                 : "=r"(r0), "=r"(r1), "=r"(r2), "=r"(r3) : "r"(a));
}

// ---------------- kernel 1: three_nn (2 threads / query, split candidates) ---
// block 256 = 128 queries x 2 scanners; grid (N/128, B) = 512 CTAs.
__global__ void knn3_kernel(const float* __restrict__ xyz1,
                            const float* __restrict__ xyz2) {
    __shared__ float4 s2[M_];
    __shared__ float  mk[128][3];
    __shared__ int    mi[128][3];
    const int b = blockIdx.y;
    const float* p2 = xyz2 + (size_t)b * M_ * 3;
    for (int j = threadIdx.x; j < M_; j += blockDim.x) {
        float x = p2[j * 3 + 0], y = p2[j * 3 + 1], z = p2[j * 3 + 2];
        s2[j] = make_float4(x, y, z, x * x + y * y + z * z);
    }
    __syncthreads();

    const int ql   = threadIdx.x >> 1;       // query within CTA
    const int half = threadIdx.x & 1;        // candidate half
    const int n = blockIdx.x * 128 + ql;
    const int p = b * N_ + n;
    const float* q = xyz1 + (size_t)p * 3;
    const float qx = q[0], qy = q[1], qz = q[2];
    const float qx2 = 2.0f * qx, qy2 = 2.0f * qy, qz2 = 2.0f * qz;
    const float sq1 = qx * qx + qy * qy + qz * qz;

    float k0 = 3.4e38f, k1 = 3.4e38f, k2 = 3.4e38f;
    int   i0 = 0, i1 = 0, i2 = 0;

    const int j0 = half * (M_ / 2);
    #pragma unroll 8
    for (int jj = 0; jj < M_ / 2; jj++) {
        const int j = j0 + jj;
        float4 v = s2[j];
        float key = v.w;
        key = fmaf(-qx2, v.x, key);
        key = fmaf(-qy2, v.y, key);
        key = fmaf(-qz2, v.z, key);
        if (key < k2) {
            if (key < k1) {
                k2 = k1; i2 = i1;
                if (key < k0) { k1 = k0; i1 = i0; k0 = key; i0 = j; }
                else          { k1 = key; i1 = j; }
            } else { k2 = key; i2 = j; }
        }
    }

    if (half == 1) {
        mk[ql][0] = k0; mk[ql][1] = k1; mk[ql][2] = k2;
        mi[ql][0] = i0; mi[ql][1] = i1; mi[ql][2] = i2;
    }
    __syncthreads();

    if (half == 0) {
        // merge own sorted triple (low indices) with partner's (high indices);
        // tie prefers low half -> matches top_k index order.
        float ak[3] = {k0, k1, k2};
        int   ai[3] = {i0, i1, i2};
        float bk[3] = {mk[ql][0], mk[ql][1], mk[ql][2]};
        int   bi[3] = {mi[ql][0], mi[ql][1], mi[ql][2]};
        float ok[3]; int oi[3];
        int ia = 0, ib = 0;
        #pragma unroll
        for (int t = 0; t < 3; t++) {
            bool ta = (ia < 3) && (ak[ia] <= bk[ib]);
            ok[t] = ta ? ak[ia] : bk[ib];
            oi[t] = ta ? ai[ia] : bi[ib];
            ia += ta ? 1 : 0;
            ib += ta ? 0 : 1;
        }
        float d0 = fmaxf(ok[0] + sq1, 1e-10f);
        float d1 = fmaxf(ok[1] + sq1, 1e-10f);
        float d2 = fmaxf(ok[2] + sq1, 1e-10f);
        float w0 = 1.0f / d0, w1 = 1.0f / d1, w2 = 1.0f / d2;
        float inv = 1.0f / (w0 + w1 + w2);
        g_idx[p * 3 + 0] = oi[0]; g_idx[p * 3 + 1] = oi[1]; g_idx[p * 3 + 2] = oi[2];
        g_w[p * 3 + 0] = w0 * inv; g_w[p * 3 + 1] = w1 * inv; g_w[p * 3 + 2] = w2 * inv;
    }
}

// ---------------- kernel 1b: transpose W -> half, [N][K] ---------------------
__global__ void transpose_half(const float* __restrict__ W, __half* __restrict__ Wt,
                               int K, int Ncols) {
    __shared__ float t[32][33];
    const int k0 = blockIdx.x * 32, n0 = blockIdx.y * 32;
    const int tx = threadIdx.x, ty = threadIdx.y;
    #pragma unroll
    for (int j = 0; j < 4; j++)
        t[ty + j * 8][tx] = W[(size_t)(k0 + ty + j * 8) * Ncols + n0 + tx];
    __syncthreads();
    #pragma unroll
    for (int j = 0; j < 4; j++)
        Wt[(size_t)(n0 + ty + j * 8) * K + k0 + tx] = __float2half_rn(t[tx][ty + j * 8]);
}

// ---------------- kernel 1c: convert points to half --------------------------
__global__ void to_half(const float* __restrict__ p2, const float* __restrict__ p1) {
    size_t t = (size_t)blockIdx.x * blockDim.x + threadIdx.x;
    const size_t n2 = (size_t)B_ * M_ * C2_ / 4;
    if (t < n2) {
        float4 v = ((const float4*)p2)[t];
        ((__half2*)g_p2h)[t * 2 + 0] = __floats2half2_rn(v.x, v.y);
        ((__half2*)g_p2h)[t * 2 + 1] = __floats2half2_rn(v.z, v.w);
    } else {
        size_t u = t - n2;
        if (u < (size_t)BNPTS * C1_ / 4) {
            float4 v = ((const float4*)p1)[u];
            ((__half2*)g_p1h)[u * 2 + 0] = __floats2half2_rn(v.x, v.y);
            ((__half2*)g_p1h)[u * 2 + 1] = __floats2half2_rn(v.z, v.w);
        }
    }
}

// ---------------- kernel 2: fused interp + MLP1 + MLP2 (fp16, ldmatrix) ------
__global__ __launch_bounds__(256, 1)
void fused_mlp(const float* __restrict__ b1,
               const float* __restrict__ b2,
               float* __restrict__ out) {
    extern __shared__ float smem[];
    int*    sIdx = (int*)smem;          // [384]
    float*  sW   = smem + 384;          // [384]
    float*  sB1  = smem + 768;          // [256]
    float*  sB2  = smem + 1024;         // [128]
    __half* U    = (__half*)(smem + META_FLOATS);

    const int tid = threadIdx.x;
    const int wid = tid >> 5, lane = tid & 31;
    const int wm = wid >> 2, wn = wid & 3;
    const int ql = lane >> 2, rl = lane & 3;
    const int R0 = blockIdx.x * 128;
    const int batch = R0 >> 13;

    const int a_r = (lane & 7) + ((lane >> 3) & 1) * 8;
    const int a_c = (lane >> 4) * 8;
    const int b_r = (lane & 7) + ((lane >> 4) << 3);
    const int b_c = ((lane >> 3) & 1) * 8;
    const uint32_t uB = smem_u32(U);

    for (int i = tid; i < 384; i += 256) {
        sIdx[i] = g_idx[R0 * 3 + i];
        sW[i]   = g_w[R0 * 3 + i];
    }
    sB1[tid] = b1[tid];
    if (tid < 128) sB2[tid] = b2[tid];
    __syncthreads();

    // ---- producer setup: 2 threads / point, 16 halves each per 32-chunk ----
    const int pr  = tid >> 1;
    const int hf0 = (tid & 1) * 16;
    const __half* pb = g_p2h + (size_t)batch * M_ * C2_;
    const __half* n0p = pb + (size_t)sIdx[pr * 3 + 0] * C2_;
    const __half* n1p = pb + (size_t)sIdx[pr * 3 + 1] * C2_;
    const __half* n2p = pb + (size_t)sIdx[pr * 3 + 2] * C2_;
    const float  pw0 = sW[pr * 3 + 0], pw1 = sW[pr * 3 + 1], pw2 = sW[pr * 3 + 2];
    const __half* p1row = g_p1h + (size_t)(R0 + pr) * C1_;

    uint4 rp[6];

    auto ldg_chunk = [&](int c) {
        if (c < 8) {
            const int off = c * 32 + hf0;
            rp[0] = *(const uint4*)(n0p + off);
            rp[1] = *(const uint4*)(n0p + off + 8);
            rp[2] = *(const uint4*)(n1p + off);
            rp[3] = *(const uint4*)(n1p + off + 8);
            rp[4] = *(const uint4*)(n2p + off);
            rp[5] = *(const uint4*)(n2p + off + 8);
        } else {
            const int off = (c - 8) * 32 + hf0;
            rp[0] = *(const uint4*)(p1row + off);
            rp[1] = *(const uint4*)(p1row + off + 8);
        }
    };
    auto sts_chunk = [&](int c, __half* Ab) {
        uint4* d = (uint4*)(Ab + pr * SA_H + hf0);
        if (c < 8) {
            const __half2* a0 = (const __half2*)&rp[0];
            const __half2* a1 = (const __half2*)&rp[2];
            const __half2* a2 = (const __half2*)&rp[4];
            __half2 o[8];
            #pragma unroll
            for (int j = 0; j < 8; j++) {
                float2 x = __half22float2(a0[j]);
                float2 y = __half22float2(a1[j]);
                float2 z = __half22float2(a2[j]);
                o[j] = __floats2half2_rn(
                    fmaf(pw0, x.x, fmaf(pw1, y.x, pw2 * z.x)),
                    fmaf(pw0, x.y, fmaf(pw1, y.y, pw2 * z.y)));
            }
            d[0] = *(uint4*)&o[0];
            d[1] = *(uint4*)&o[4];
        } else {
            d[0] = rp[0];
            d[1] = rp[1];
        }
    };
    auto ldB1 = [&](int c) {
        __half* dst = U + OFF_B1 + (c % 3) * B1_BUFH;
        const __half* src = g_W1t + c * 32;
        const uint32_t da = smem_u32(dst);
        #pragma unroll
        for (int i = 0; i < 4; i++) {
            int seg = tid + i * 256;
            int n = seg >> 2, s = seg & 3;
            cp_async16(da + (n * SA_H + s * 8) * 2, src + (size_t)n * CIN_ + s * 8);
        }
        cp_commit();
    };
    auto ldW2 = [&](int c) {
        if (c < NC2) {
            __half* dst = U + OFF_W2 + (c % 3) * W2_BUFH;
            const __half* src = g_W2t + c * 32;
            const uint32_t da = smem_u32(dst);
            #pragma unroll
            for (int i = 0; i < 2; i++) {
                int seg = tid + i * 256;
                int n = seg >> 2, s = seg & 3;
                cp_async16(da + (n * SA_H + s * 8) * 2, src + (size_t)n * H1_ + s * 8);
            }
        }
        cp_commit();
    };

    // ---- phase 1: warp tile 64x64, 4(m) x 8(n) frags ----
    float acc[4][8][4];
    #pragma unroll
    for (int i = 0; i < 4; i++)
        #pragma unroll
        for (int j = 0; j < 8; j++)
            #pragma unroll
            for (int e = 0; e < 4; e++) acc[i][j][e] = 0.0f;

    ldg_chunk(0);
    sts_chunk(0, U + OFF_A0);
    ldB1(0);
    ldB1(1);

    #pragma unroll 1
    for (int c = 0; c < NC1; c++) {
        if (c + 1 < NC1) ldg_chunk(c + 1);   // gather early: covered by wait+MMA
        cp_wait<1>();
        __syncthreads();

        const uint32_t aBase = uB + ((c & 1) ? OFF_A1 : OFF_A0) * 2;
        const uint32_t bBase = uB + (OFF_B1 + (c % 3) * B1_BUFH) * 2;
        #pragma unroll
        for (int ks = 0; ks < 2; ks++) {
            uint32_t af[4][4], bf[8][2];
            #pragma unroll
            for (int mt = 0; mt < 4; mt++)
                ldsm_x4(af[mt][0], af[mt][1], af[mt][2], af[mt][3],
                        aBase + ((wm * 64 + mt * 16 + a_r) * SA_H + ks * 16 + a_c) * 2);
            #pragma unroll
            for (int g = 0; g < 4; g++)
                ldsm_x4(bf[2 * g][0], bf[2 * g][1], bf[2 * g + 1][0], bf[2 * g + 1][1],
                        bBase + ((wn * 64 + g * 16 + b_r) * SA_H + ks * 16 + b_c) * 2);
            #pragma unroll
            for (int mt = 0; mt < 4; mt++)
                #pragma unroll
                for (int nt = 0; nt < 8; nt++)
                    mma_f16(acc[mt][nt], af[mt], bf[nt]);
        }

        if (c + 1 < NC1) sts_chunk(c + 1, U + (((c + 1) & 1) ? OFF_A1 : OFF_A0));
        if (c + 2 < NC1)        ldB1(c + 2);
        else if (c + 2 == NC1)  ldW2(0);
        else                    ldW2(1);
    }

    __syncthreads();

    // ---- phase-1 epilogue: bias+relu -> h (half, SMEM); W2_0/1 in flight ----
    __half* hS = U + OFF_H;
    #pragma unroll
    for (int nt = 0; nt < 8; nt++) {
        const int cb = wn * 64 + nt * 8 + rl * 2;
        const float bx = sB1[cb], by = sB1[cb + 1];
        #pragma unroll
        for (int mt = 0; mt < 4; mt++) {
            const int r0 = wm * 64 + mt * 16 + ql;
            *(__half2*)(hS + r0 * HSTR_H + cb) =
                __floats2half2_rn(fmaxf(acc[mt][nt][0] + bx, 0.0f),
                                  fmaxf(acc[mt][nt][1] + by, 0.0f));
            *(__half2*)(hS + (r0 + 8) * HSTR_H + cb) =
                __floats2half2_rn(fmaxf(acc[mt][nt][2] + bx, 0.0f),
                                  fmaxf(acc[mt][nt][3] + by, 0.0f));
        }
    }
    __syncthreads();

    // ---- phase 2: out = relu(h @ W2 + b2); warp tile 64x32 ----
    float acc2[4][4][4];
    #pragma unroll
    for (int i = 0; i < 4; i++)
        #pragma unroll
        for (int j = 0; j < 4; j++)
            #pragma unroll
            for (int e = 0; e < 4; e++) acc2[i][j][e] = 0.0f;

    #pragma unroll 1
    for (int nc = 0; nc < NC2; nc++) {
        cp_wait<1>();
        __syncthreads();
        const uint32_t bBase = uB + (OFF_W2 + (nc % 3) * W2_BUFH) * 2;
        #pragma unroll
        for (int ks = 0; ks < 2; ks++) {
            uint32_t af[4][4], bf[4][2];
            #pragma unroll
            for (int mt = 0; mt < 4; mt++)
                ldsm_x4(af[mt][0], af[mt][1], af[mt][2], af[mt][3],
                        uB + ((wm * 64 + mt * 16 + a_r) * HSTR_H
                              + nc * 32 + ks * 16 + a_c) * 2);
            #pragma unroll
            for (int g = 0; g < 2; g++)
                ldsm_x4(bf[2 * g][0], bf[2 * g][1], bf[2 * g + 1][0], bf[2 * g + 1][1],
                        bBase + ((wn * 32 + g * 16 + b_r) * SA_H + ks * 16 + b_c) * 2);
            #pragma unroll
            for (int mt = 0; mt < 4; mt++)
                #pragma unroll
                for (int nt = 0; nt < 4; nt++)
                    mma_f16(acc2[mt][nt], af[mt], bf[nt]);
        }
        ldW2(nc + 2);
    }

    // ---- phase-2 epilogue ----
    float* outB = out + (size_t)R0 * H2_;
    #pragma unroll
    for (int nt = 0; nt < 4; nt++) {
        const int cb = wn * 32 + nt * 8 + rl * 2;
        const float bx = sB2[cb], by = sB2[cb + 1];
        #pragma unroll
        for (int mt = 0; mt < 4; mt++) {
            const int r0 = wm * 64 + mt * 16 + ql;
            float v0 = fmaxf(acc2[mt][nt][0] + bx, 0.0f);
            float v1 = fmaxf(acc2[mt][nt][1] + by, 0.0f);
            float v2 = fmaxf(acc2[mt][nt][2] + bx, 0.0f);
            float v3 = fmaxf(acc2[mt][nt][3] + by, 0.0f);
            *(float2*)(outB + (size_t)r0 * H2_ + cb)       = make_float2(v0, v1);
            *(float2*)(outB + (size_t)(r0 + 8) * H2_ + cb) = make_float2(v2, v3);
        }
    }
}

// ---------------- launch ------------------------------------------------------
extern "C" void kernel_launch(void* const* d_in, const int* in_sizes, int n_in,
                              void* d_out, int out_size) {
    const float* xyz1    = (const float*)d_in[0];
    const float* xyz2    = (const float*)d_in[1];
    const float* points1 = (const float*)d_in[2];
    const float* points2 = (const float*)d_in[3];
    const float* W1      = (const float*)d_in[4];
    const float* b1      = (const float*)d_in[5];
    const float* W2      = (const float*)d_in[6];
    const float* b2      = (const float*)d_in[7];
    float* out = (float*)d_out;

    __half *gw1, *gw2;
    cudaGetSymbolAddress((void**)&gw1, g_W1t);
    cudaGetSymbolAddress((void**)&gw2, g_W2t);

    cudaFuncSetAttribute(fused_mlp,
                         cudaFuncAttributeMaxDynamicSharedMemorySize, SMEM_BYTES);

    // 1) prep: weight transposes + point conversion + three_nn
    transpose_half<<<dim3(CIN_ / 32, H1_ / 32), dim3(32, 8)>>>(W1, gw1, CIN_, H1_);
    transpose_half<<<dim3(H1_ / 32, H2_ / 32), dim3(32, 8)>>>(W2, gw2, H1_, H2_);
    {
        const size_t tot = (size_t)B_ * M_ * C2_ / 4 + (size_t)BNPTS * C1_ / 4;
        to_half<<<(unsigned)((tot + 255) / 256), 256>>>(points2, points1);
    }
    dim3 g1(N_ / 128, B_);
    knn3_kernel<<<g1, 256>>>(xyz1, xyz2);

    // 2) fused interp + MLP (512 CTAs of 128 points)
    fused_mlp<<<BNPTS / 128, 256, SMEM_BYTES>>>(b1, b2, out);
}

// round 17
// speedup vs baseline: 1.5519x; 1.5519x over previous
#include <cuda_runtime.h>
#include <cuda_fp16.h>
#include <cstdint>

#define B_    8
#define N_    8192
#define M_    2048
#define C1_   128
#define C2_   256
#define H1_   256
#define H2_   128
#define CIN_  (C2_ + C1_)   // 384
#define BNPTS (B_ * N_)     // 65536
#define NC1   12            // K chunks layer 1 (384/32)
#define NC2   8             // K chunks layer 2 (256/32)

// strides in HALVES, conflict-free for ldmatrix
#define SA_H   40    // A / B1 / W2 chunk row stride
#define HSTR_H 264   // h row stride

#define A_BUFH  (128 * SA_H)     // 5120 halves
#define B1_BUFH (256 * SA_H)     // 10240
#define W2_BUFH (128 * SA_H)     // 5120
#define OFF_A0  0
#define OFF_A1  A_BUFH
#define OFF_B1  (2 * A_BUFH)               // 10240, 3 bufs -> ends 40960
#define OFF_H   0                          // overlays A + B1 region
#define OFF_W2  (OFF_B1 + 3 * B1_BUFH)     // 40960, 3 bufs (non-overlapping)
#define U_HALVES (OFF_W2 + 3 * W2_BUFH)    // 56320 halves = 112640 B
#define META_FLOATS 1152
#define SMEM_BYTES (META_FLOATS * 4 + U_HALVES * 2)   // 117248

// ---------------- scratch ----------------------------------------------------
__device__ int    g_idx[BNPTS * 3];
__device__ float  g_w[BNPTS * 3];
__device__ float  g_pk[BNPTS * 6];            // partial keys  [p][half][3]
__device__ int    g_pi[BNPTS * 6];            // partial idx   [p][half][3]
__device__ __half g_W1t[H1_ * CIN_];          // W1^T [n][k]
__device__ __half g_W2t[H2_ * H1_];           // W2^T [n][k]
__device__ __half g_p2h[B_ * M_ * C2_];       // points2 as half
__device__ __half g_p1h[(size_t)BNPTS * C1_]; // points1 as half

__device__ __forceinline__ void cp_async16(uint32_t dst, const void* src) {
    asm volatile("cp.async.ca.shared.global [%0], [%1], 16;"
                 :: "r"(dst), "l"(src) : "memory");
}
__device__ __forceinline__ void cp_commit() {
    asm volatile("cp.async.commit_group;" ::: "memory");
}
template<int NWAIT>
__device__ __forceinline__ void cp_wait() {
    asm volatile("cp.async.wait_group %0;" :: "n"(NWAIT) : "memory");
}
__device__ __forceinline__ uint32_t smem_u32(const void* p) {
    uint32_t a;
    asm("{ .reg .u64 t; cvta.to.shared.u64 t, %1; cvt.u32.u64 %0, t; }" : "=r"(a) : "l"(p));
    return a;
}
__device__ __forceinline__ void mma_f16(float* c, const uint32_t* a,
                                        const uint32_t* b) {
    asm volatile(
        "mma.sync.aligned.m16n8k16.row.col.f32.f16.f16.f32 "
        "{%0,%1,%2,%3}, {%4,%5,%6,%7}, {%8,%9}, {%0,%1,%2,%3};"
        : "+f"(c[0]), "+f"(c[1]), "+f"(c[2]), "+f"(c[3])
        : "r"(a[0]), "r"(a[1]), "r"(a[2]), "r"(a[3]), "r"(b[0]), "r"(b[1]));
}
__device__ __forceinline__ void ldsm_x4(uint32_t& r0, uint32_t& r1,
                                        uint32_t& r2, uint32_t& r3, uint32_t a) {
    asm volatile("ldmatrix.sync.aligned.m8n8.x4.shared.b16 {%0,%1,%2,%3}, [%4];"
                 : "=r"(r0), "=r"(r1), "=r"(r2), "=r"(r3) : "r"(a));
}

// ---------------- kernel 1: three_nn scan (CTA-level candidate split) --------
// grid (N/256, B, 2); 256 threads; 1 query/thread; broadcast-preserving.
__global__ void knn3_scan(const float* __restrict__ xyz1,
                          const float* __restrict__ xyz2) {
    __shared__ float4 s2[M_ / 2];
    const int b = blockIdx.y;
    const int half = blockIdx.z;
    const float* p2 = xyz2 + ((size_t)b * M_ + half * (M_ / 2)) * 3;
    for (int j = threadIdx.x; j < M_ / 2; j += blockDim.x) {
        float x = p2[j * 3 + 0], y = p2[j * 3 + 1], z = p2[j * 3 + 2];
        s2[j] = make_float4(x, y, z, x * x + y * y + z * z);
    }
    __syncthreads();

    const int n = blockIdx.x * blockDim.x + threadIdx.x;
    const int p = b * N_ + n;
    const float* q = xyz1 + (size_t)p * 3;
    const float qx2 = 2.0f * q[0], qy2 = 2.0f * q[1], qz2 = 2.0f * q[2];

    float k0 = 3.4e38f, k1 = 3.4e38f, k2 = 3.4e38f;
    int   i0 = 0, i1 = 0, i2 = 0;

    #pragma unroll 8
    for (int j = 0; j < M_ / 2; j++) {
        float4 v = s2[j];
        float key = v.w;
        key = fmaf(-qx2, v.x, key);
        key = fmaf(-qy2, v.y, key);
        key = fmaf(-qz2, v.z, key);
        if (key < k2) {
            if (key < k1) {
                k2 = k1; i2 = i1;
                if (key < k0) { k1 = k0; i1 = i0; k0 = key; i0 = j; }
                else          { k1 = key; i1 = j; }
            } else { k2 = key; i2 = j; }
        }
    }

    const int base = p * 6 + half * 3;
    const int joff = half * (M_ / 2);
    g_pk[base + 0] = k0; g_pk[base + 1] = k1; g_pk[base + 2] = k2;
    g_pi[base + 0] = i0 + joff; g_pi[base + 1] = i1 + joff; g_pi[base + 2] = i2 + joff;
}

// ---------------- kernel 1m: merge halves + weights --------------------------
__global__ void knn3_merge(const float* __restrict__ xyz1) {
    const int p = blockIdx.x * blockDim.x + threadIdx.x;
    if (p >= BNPTS) return;
    const float* q = xyz1 + (size_t)p * 3;
    const float sq1 = q[0] * q[0] + q[1] * q[1] + q[2] * q[2];

    float ak[3], bk[3];
    int   ai[3], bi[3];
    #pragma unroll
    for (int t = 0; t < 3; t++) {
        ak[t] = g_pk[p * 6 + t];     ai[t] = g_pi[p * 6 + t];
        bk[t] = g_pk[p * 6 + 3 + t]; bi[t] = g_pi[p * 6 + 3 + t];
    }
    float ok[3]; int oi[3];
    int ia = 0, ib = 0;
    #pragma unroll
    for (int t = 0; t < 3; t++) {
        bool ta = (ib >= 3) || ((ia < 3) && (ak[ia] <= bk[ib]));
        ok[t] = ta ? ak[ia] : bk[ib];
        oi[t] = ta ? ai[ia] : bi[ib];
        ia += ta ? 1 : 0;
        ib += ta ? 0 : 1;
    }
    float d0 = fmaxf(ok[0] + sq1, 1e-10f);
    float d1 = fmaxf(ok[1] + sq1, 1e-10f);
    float d2 = fmaxf(ok[2] + sq1, 1e-10f);
    float w0 = 1.0f / d0, w1 = 1.0f / d1, w2 = 1.0f / d2;
    float inv = 1.0f / (w0 + w1 + w2);
    g_idx[p * 3 + 0] = oi[0]; g_idx[p * 3 + 1] = oi[1]; g_idx[p * 3 + 2] = oi[2];
    g_w[p * 3 + 0] = w0 * inv; g_w[p * 3 + 1] = w1 * inv; g_w[p * 3 + 2] = w2 * inv;
}

// ---------------- kernel 1b: transpose W -> half, [N][K] ---------------------
__global__ void transpose_half(const float* __restrict__ W, __half* __restrict__ Wt,
                               int K, int Ncols) {
    __shared__ float t[32][33];
    const int k0 = blockIdx.x * 32, n0 = blockIdx.y * 32;
    const int tx = threadIdx.x, ty = threadIdx.y;
    #pragma unroll
    for (int j = 0; j < 4; j++)
        t[ty + j * 8][tx] = W[(size_t)(k0 + ty + j * 8) * Ncols + n0 + tx];
    __syncthreads();
    #pragma unroll
    for (int j = 0; j < 4; j++)
        Wt[(size_t)(n0 + ty + j * 8) * K + k0 + tx] = __float2half_rn(t[tx][ty + j * 8]);
}

// ---------------- kernel 1c: convert points to half --------------------------
__global__ void to_half(const float* __restrict__ p2, const float* __restrict__ p1) {
    size_t t = (size_t)blockIdx.x * blockDim.x + threadIdx.x;
    const size_t n2 = (size_t)B_ * M_ * C2_ / 4;
    if (t < n2) {
        float4 v = ((const float4*)p2)[t];
        ((__half2*)g_p2h)[t * 2 + 0] = __floats2half2_rn(v.x, v.y);
        ((__half2*)g_p2h)[t * 2 + 1] = __floats2half2_rn(v.z, v.w);
    } else {
        size_t u = t - n2;
        if (u < (size_t)BNPTS * C1_ / 4) {
            float4 v = ((const float4*)p1)[u];
            ((__half2*)g_p1h)[u * 2 + 0] = __floats2half2_rn(v.x, v.y);
            ((__half2*)g_p1h)[u * 2 + 1] = __floats2half2_rn(v.z, v.w);
        }
    }
}

// ---------------- kernel 2: fused interp + MLP1 + MLP2 (fp16, ldmatrix) ------
__global__ __launch_bounds__(256, 1)
void fused_mlp(const float* __restrict__ b1,
               const float* __restrict__ b2,
               float* __restrict__ out) {
    extern __shared__ float smem[];
    int*    sIdx = (int*)smem;          // [384]
    float*  sW   = smem + 384;          // [384]
    float*  sB1  = smem + 768;          // [256]
    float*  sB2  = smem + 1024;         // [128]
    __half* U    = (__half*)(smem + META_FLOATS);

    const int tid = threadIdx.x;
    const int wid = tid >> 5, lane = tid & 31;
    const int wm = wid >> 2, wn = wid & 3;
    const int ql = lane >> 2, rl = lane & 3;
    const int R0 = blockIdx.x * 128;
    const int batch = R0 >> 13;

    const int a_r = (lane & 7) + ((lane >> 3) & 1) * 8;
    const int a_c = (lane >> 4) * 8;
    const int b_r = (lane & 7) + ((lane >> 4) << 3);
    const int b_c = ((lane >> 3) & 1) * 8;
    const uint32_t uB = smem_u32(U);

    for (int i = tid; i < 384; i += 256) {
        sIdx[i] = g_idx[R0 * 3 + i];
        sW[i]   = g_w[R0 * 3 + i];
    }
    sB1[tid] = b1[tid];
    if (tid < 128) sB2[tid] = b2[tid];
    __syncthreads();

    // ---- producer setup: 2 threads / point, 16 halves each per 32-chunk ----
    const int pr  = tid >> 1;
    const int hf0 = (tid & 1) * 16;
    const __half* pb = g_p2h + (size_t)batch * M_ * C2_;
    const __half* n0p = pb + (size_t)sIdx[pr * 3 + 0] * C2_;
    const __half* n1p = pb + (size_t)sIdx[pr * 3 + 1] * C2_;
    const __half* n2p = pb + (size_t)sIdx[pr * 3 + 2] * C2_;
    const float  pw0 = sW[pr * 3 + 0], pw1 = sW[pr * 3 + 1], pw2 = sW[pr * 3 + 2];
    const __half* p1row = g_p1h + (size_t)(R0 + pr) * C1_;

    uint4 rp[6];

    auto ldg_chunk = [&](int c) {
        if (c < 8) {
            const int off = c * 32 + hf0;
            rp[0] = *(const uint4*)(n0p + off);
            rp[1] = *(const uint4*)(n0p + off + 8);
            rp[2] = *(const uint4*)(n1p + off);
            rp[3] = *(const uint4*)(n1p + off + 8);
            rp[4] = *(const uint4*)(n2p + off);
            rp[5] = *(const uint4*)(n2p + off + 8);
        } else {
            const int off = (c - 8) * 32 + hf0;
            rp[0] = *(const uint4*)(p1row + off);
            rp[1] = *(const uint4*)(p1row + off + 8);
        }
    };
    auto sts_chunk = [&](int c, __half* Ab) {
        uint4* d = (uint4*)(Ab + pr * SA_H + hf0);
        if (c < 8) {
            const __half2* a0 = (const __half2*)&rp[0];
            const __half2* a1 = (const __half2*)&rp[2];
            const __half2* a2 = (const __half2*)&rp[4];
            __half2 o[8];
            #pragma unroll
            for (int j = 0; j < 8; j++) {
                float2 x = __half22float2(a0[j]);
                float2 y = __half22float2(a1[j]);
                float2 z = __half22float2(a2[j]);
                o[j] = __floats2half2_rn(
                    fmaf(pw0, x.x, fmaf(pw1, y.x, pw2 * z.x)),
                    fmaf(pw0, x.y, fmaf(pw1, y.y, pw2 * z.y)));
            }
            d[0] = *(uint4*)&o[0];
            d[1] = *(uint4*)&o[4];
        } else {
            d[0] = rp[0];
            d[1] = rp[1];
        }
    };
    auto ldB1 = [&](int c) {
        __half* dst = U + OFF_B1 + (c % 3) * B1_BUFH;
        const __half* src = g_W1t + c * 32;
        const uint32_t da = smem_u32(dst);
        #pragma unroll
        for (int i = 0; i < 4; i++) {
            int seg = tid + i * 256;
            int n = seg >> 2, s = seg & 3;
            cp_async16(da + (n * SA_H + s * 8) * 2, src + (size_t)n * CIN_ + s * 8);
        }
        cp_commit();
    };
    auto ldW2 = [&](int c) {
        if (c < NC2) {
            __half* dst = U + OFF_W2 + (c % 3) * W2_BUFH;
            const __half* src = g_W2t + c * 32;
            const uint32_t da = smem_u32(dst);
            #pragma unroll
            for (int i = 0; i < 2; i++) {
                int seg = tid + i * 256;
                int n = seg >> 2, s = seg & 3;
                cp_async16(da + (n * SA_H + s * 8) * 2, src + (size_t)n * H1_ + s * 8);
            }
        }
        cp_commit();
    };

    // ---- phase 1: warp tile 64x64, 4(m) x 8(n) frags ----
    float acc[4][8][4];
    #pragma unroll
    for (int i = 0; i < 4; i++)
        #pragma unroll
        for (int j = 0; j < 8; j++)
            #pragma unroll
            for (int e = 0; e < 4; e++) acc[i][j][e] = 0.0f;

    ldg_chunk(0);
    sts_chunk(0, U + OFF_A0);
    ldB1(0);
    ldB1(1);

    #pragma unroll 1
    for (int c = 0; c < NC1; c++) {
        if (c + 1 < NC1) ldg_chunk(c + 1);   // gather early: covered by wait+MMA
        cp_wait<1>();
        __syncthreads();

        const uint32_t aBase = uB + ((c & 1) ? OFF_A1 : OFF_A0) * 2;
        const uint32_t bBase = uB + (OFF_B1 + (c % 3) * B1_BUFH) * 2;
        #pragma unroll
        for (int ks = 0; ks < 2; ks++) {
            uint32_t af[4][4], bf[8][2];
            #pragma unroll
            for (int mt = 0; mt < 4; mt++)
                ldsm_x4(af[mt][0], af[mt][1], af[mt][2], af[mt][3],
                        aBase + ((wm * 64 + mt * 16 + a_r) * SA_H + ks * 16 + a_c) * 2);
            #pragma unroll
            for (int g = 0; g < 4; g++)
                ldsm_x4(bf[2 * g][0], bf[2 * g][1], bf[2 * g + 1][0], bf[2 * g + 1][1],
                        bBase + ((wn * 64 + g * 16 + b_r) * SA_H + ks * 16 + b_c) * 2);
            #pragma unroll
            for (int mt = 0; mt < 4; mt++)
                #pragma unroll
                for (int nt = 0; nt < 8; nt++)
                    mma_f16(acc[mt][nt], af[mt], bf[nt]);
        }

        if (c + 1 < NC1) sts_chunk(c + 1, U + (((c + 1) & 1) ? OFF_A1 : OFF_A0));
        if (c + 2 < NC1)        ldB1(c + 2);
        else if (c + 2 == NC1)  ldW2(0);
        else                    ldW2(1);
    }

    __syncthreads();

    // ---- phase-1 epilogue: bias+relu -> h (half, SMEM); W2_0/1 in flight ----
    __half* hS = U + OFF_H;
    #pragma unroll
    for (int nt = 0; nt < 8; nt++) {
        const int cb = wn * 64 + nt * 8 + rl * 2;
        const float bx = sB1[cb], by = sB1[cb + 1];
        #pragma unroll
        for (int mt = 0; mt < 4; mt++) {
            const int r0 = wm * 64 + mt * 16 + ql;
            *(__half2*)(hS + r0 * HSTR_H + cb) =
                __floats2half2_rn(fmaxf(acc[mt][nt][0] + bx, 0.0f),
                                  fmaxf(acc[mt][nt][1] + by, 0.0f));
            *(__half2*)(hS + (r0 + 8) * HSTR_H + cb) =
                __floats2half2_rn(fmaxf(acc[mt][nt][2] + bx, 0.0f),
                                  fmaxf(acc[mt][nt][3] + by, 0.0f));
        }
    }
    __syncthreads();

    // ---- phase 2: out = relu(h @ W2 + b2); warp tile 64x32 ----
    float acc2[4][4][4];
    #pragma unroll
    for (int i = 0; i < 4; i++)
        #pragma unroll
        for (int j = 0; j < 4; j++)
            #pragma unroll
            for (int e = 0; e < 4; e++) acc2[i][j][e] = 0.0f;

    #pragma unroll 1
    for (int nc = 0; nc < NC2; nc++) {
        cp_wait<1>();
        __syncthreads();
        const uint32_t bBase = uB + (OFF_W2 + (nc % 3) * W2_BUFH) * 2;
        #pragma unroll
        for (int ks = 0; ks < 2; ks++) {
            uint32_t af[4][4], bf[4][2];
            #pragma unroll
            for (int mt = 0; mt < 4; mt++)
                ldsm_x4(af[mt][0], af[mt][1], af[mt][2], af[mt][3],
                        uB + ((wm * 64 + mt * 16 + a_r) * HSTR_H
                              + nc * 32 + ks * 16 + a_c) * 2);
            #pragma unroll
            for (int g = 0; g < 2; g++)
                ldsm_x4(bf[2 * g][0], bf[2 * g][1], bf[2 * g + 1][0], bf[2 * g + 1][1],
                        bBase + ((wn * 32 + g * 16 + b_r) * SA_H + ks * 16 + b_c) * 2);
            #pragma unroll
            for (int mt = 0; mt < 4; mt++)
                #pragma unroll
                for (int nt = 0; nt < 4; nt++)
                    mma_f16(acc2[mt][nt], af[mt], bf[nt]);
        }
        ldW2(nc + 2);
    }

    // ---- phase-2 epilogue ----
    float* outB = out + (size_t)R0 * H2_;
    #pragma unroll
    for (int nt = 0; nt < 4; nt++) {
        const int cb = wn * 32 + nt * 8 + rl * 2;
        const float bx = sB2[cb], by = sB2[cb + 1];
        #pragma unroll
        for (int mt = 0; mt < 4; mt++) {
            const int r0 = wm * 64 + mt * 16 + ql;
            float v0 = fmaxf(acc2[mt][nt][0] + bx, 0.0f);
            float v1 = fmaxf(acc2[mt][nt][1] + by, 0.0f);
            float v2 = fmaxf(acc2[mt][nt][2] + bx, 0.0f);
            float v3 = fmaxf(acc2[mt][nt][3] + by, 0.0f);
            *(float2*)(outB + (size_t)r0 * H2_ + cb)       = make_float2(v0, v1);
            *(float2*)(outB + (size_t)(r0 + 8) * H2_ + cb) = make_float2(v2, v3);
        }
    }
}

// ---------------- launch ------------------------------------------------------
extern "C" void kernel_launch(void* const* d_in, const int* in_sizes, int n_in,
                              void* d_out, int out_size) {
    const float* xyz1    = (const float*)d_in[0];
    const float* xyz2    = (const float*)d_in[1];
    const float* points1 = (const float*)d_in[2];
    const float* points2 = (const float*)d_in[3];
    const float* W1      = (const float*)d_in[4];
    const float* b1      = (const float*)d_in[5];
    const float* W2      = (const float*)d_in[6];
    const float* b2      = (const float*)d_in[7];
    float* out = (float*)d_out;

    __half *gw1, *gw2;
    cudaGetSymbolAddress((void**)&gw1, g_W1t);
    cudaGetSymbolAddress((void**)&gw2, g_W2t);

    cudaFuncSetAttribute(fused_mlp,
                         cudaFuncAttributeMaxDynamicSharedMemorySize, SMEM_BYTES);

    // 1) prep: weight transposes + point conversion + three_nn (scan + merge)
    transpose_half<<<dim3(CIN_ / 32, H1_ / 32), dim3(32, 8)>>>(W1, gw1, CIN_, H1_);
    transpose_half<<<dim3(H1_ / 32, H2_ / 32), dim3(32, 8)>>>(W2, gw2, H1_, H2_);
    {
        const size_t tot = (size_t)B_ * M_ * C2_ / 4 + (size_t)BNPTS * C1_ / 4;
        to_half<<<(unsigned)((tot + 255) / 256), 256>>>(points2, points1);
    }
    dim3 gScan(N_ / 256, B_, 2);
    knn3_scan<<<gScan, 256>>>(xyz1, xyz2);
    knn3_merge<<<BNPTS / 256, 256>>>(xyz1);

    // 2) fused interp + MLP (512 CTAs of 128 points)
    fused_mlp<<<BNPTS / 128, 256, SMEM_BYTES>>>(b1, b2, out);
}